// round 6
// baseline (speedup 1.0000x reference)
#include <cuda_runtime.h>
#include <cuda_bf16.h>

// Problem constants
#define KSZ   9
#define PAD   4
#define H     256
#define W     256
#define HO    248
#define WO    248
#define B     4
#define PLANE (H * W)

// Tiling: block = 64x8 outputs over the FULL image; warp = one row, 2 cols/lane.
// Symmetric half-space formulation: offsets o = (0,1..4) and (1..4,-4..4) = 40 taps.
#define TW    64
#define TH    8
#define SW    72           // cols gc-4 .. gc+TW+3
#define SH    12           // rows r .. r+TH+3  (halo below only)
#define NTHR  256

#define GX    4
#define GY    32           // full 256 rows
#define NBLK  (GX * GY * B)   // 512

// -100 * log2(e) : exp(-color/0.01) = 2^(color * NC1)
#define NC1   (-144.26950408889634f)
// log2(e)/9      : dist = 2^(-d2_spatial * DC)
#define DC    (1.4426950408889634f / 9.0f)

typedef unsigned long long ull;

static __device__ float        g_bsums[NBLK];
static __device__ unsigned int g_count = 0;

__device__ __forceinline__ float ex2f(float v) {
    float r;
    asm("ex2.approx.f32 %0, %1;" : "=f"(r) : "f"(v));
    return r;
}
__device__ __forceinline__ ull pk(float lo, float hi) {
    ull r;
    asm("mov.b64 %0, {%1, %2};" : "=l"(r) : "f"(lo), "f"(hi));
    return r;
}
__device__ __forceinline__ void upk(ull v, float& lo, float& hi) {
    asm("mov.b64 {%0, %1}, %2;" : "=f"(lo), "=f"(hi) : "l"(v));
}
__device__ __forceinline__ ull f2add(ull a, ull b) {
    ull r;
    asm("add.rn.f32x2 %0, %1, %2;" : "=l"(r) : "l"(a), "l"(b));
    return r;
}
__device__ __forceinline__ ull f2mul(ull a, ull b) {
    ull r;
    asm("mul.rn.f32x2 %0, %1, %2;" : "=l"(r) : "l"(a), "l"(b));
    return r;
}
__device__ __forceinline__ ull f2fma(ull a, ull b, ull c) {
    ull r;
    asm("fma.rn.f32x2 %0, %1, %2, %3;" : "=l"(r) : "l"(a), "l"(b), "l"(c));
    return r;
}

// Per-thread compute over the 40 half-space offsets for a packed column pair.
// INTERIOR: every p in tile and every q=p+o are interior -> factor 2 folded out.
// Border:   total = pInF * (Sum w*m) + Sum w*m*qInF + pInF * 2*y0*y1(center).
template <bool INTERIOR>
__device__ __forceinline__ float compute_pair(
    float (&s)[5][SH][SW], int ly, int lx2, int gr, int gc0)
{
    const ull negc0 = pk(-s[0][ly][lx2 + 4], -s[0][ly][lx2 + 5]);
    const ull negc1 = pk(-s[1][ly][lx2 + 4], -s[1][ly][lx2 + 5]);
    const ull negc2 = pk(-s[2][ly][lx2 + 4], -s[2][ly][lx2 + 5]);
    const float y0c0 = s[3][ly][lx2 + 4], y0c1 = s[3][ly][lx2 + 5];
    const float y1c0 = s[4][ly][lx2 + 4], y1c1 = s[4][ly][lx2 + 5];
    const ull y0c_pk = pk(y0c0, y0c1);
    const ull y1c_pk = pk(y1c0, y1c1);

    ull accA = 0ull;   // Sum w * y1_q   (packed over col pair)
    ull accB = 0ull;   // Sum w * y0_q
    ull acc2 = 0ull;   // border only: Sum w * m * qInF

    #pragma unroll
    for (int di = 0; di < 5; di++) {
        const int sr = ly + di;
        float v0[10], v1[10], v2[10], q0[10], q1[10];
        const int m0 = (di == 0) ? 2 : 0;   // di==0 needs only cols +4..+9
        #pragma unroll
        for (int m = m0; m < 5; m++) {
            float2 t;
            t = *(const float2*)&s[0][sr][lx2 + 2*m]; v0[2*m] = t.x; v0[2*m+1] = t.y;
            t = *(const float2*)&s[1][sr][lx2 + 2*m]; v1[2*m] = t.x; v1[2*m+1] = t.y;
            t = *(const float2*)&s[2][sr][lx2 + 2*m]; v2[2*m] = t.x; v2[2*m+1] = t.y;
            t = *(const float2*)&s[3][sr][lx2 + 2*m]; q0[2*m] = t.x; q0[2*m+1] = t.y;
            t = *(const float2*)&s[4][sr][lx2 + 2*m]; q1[2*m] = t.x; q1[2*m+1] = t.y;
        }
        bool rqOK = true;
        if (!INTERIOR) {
            const int rq = gr + di;
            rqOK = (rq >= 4) && (rq <= 251);
        }
        const int djs = (di == 0) ? 1 : -4;
        #pragma unroll
        for (int dj = djs; dj <= 4; dj++) {
            const int j = dj + 4;
            ull n0 = pk(v0[j], v0[j + 1]);
            ull n1 = pk(v1[j], v1[j + 1]);
            ull n2 = pk(v2[j], v2[j + 1]);
            ull d0 = f2add(n0, negc0);
            ull d1 = f2add(n1, negc1);
            ull d2 = f2add(n2, negc2);
            ull c  = f2mul(d0, d0);
            c = f2fma(d1, d1, c);
            c = f2fma(d2, d2, c);
            float clo, chi;
            upk(c, clo, chi);
            const float c0k = -(float)(di * di + dj * dj) * DC;
            ull w = pk(ex2f(fmaf(clo, NC1, c0k)), ex2f(fmaf(chi, NC1, c0k)));
            ull ny0 = pk(q0[j], q0[j + 1]);
            ull ny1 = pk(q1[j], q1[j + 1]);
            accA = f2fma(w, ny1, accA);
            accB = f2fma(w, ny0, accB);
            if (!INTERIOR) {
                ull m2 = f2fma(y1c_pk, ny0, f2mul(y0c_pk, ny1));
                float qf0 = (rqOK && (unsigned)(gc0 + dj - 4) <= 247u) ? 1.0f : 0.0f;
                float qf1 = (rqOK && (unsigned)(gc0 + 1 + dj - 4) <= 247u) ? 1.0f : 0.0f;
                acc2 = f2fma(w, f2mul(m2, pk(qf0, qf1)), acc2);
            }
        }
    }

    float a0, a1, b0, b1;
    upk(accA, a0, a1);
    upk(accB, b0, b1);
    const float tc0 = y0c0 * y1c0;   // center (o=0): contributes [p in I]*2*y0*y1
    const float tc1 = y0c1 * y1c1;

    if (INTERIOR) {
        // all p,q interior -> factor 2 on every pair incl. center
        return 2.0f * (fmaf(y0c0, a0, fmaf(y1c0, b0, tc0)) +
                       fmaf(y0c1, a1, fmaf(y1c1, b1, tc1)));
    } else {
        const bool rOK = (unsigned)(gr - 4) <= 247u;
        const float p0f = (rOK && (unsigned)(gc0 - 4) <= 247u) ? 1.0f : 0.0f;
        const float p1f = (rOK && (unsigned)(gc0 - 3) <= 247u) ? 1.0f : 0.0f;
        float c20, c21;
        upk(acc2, c20, c21);
        const float t0 = fmaf(y0c0, a0, fmaf(y1c0, b0, 2.0f * tc0));
        const float t1 = fmaf(y0c1, a1, fmaf(y1c1, b1, 2.0f * tc1));
        return fmaf(p0f, t0, fmaf(p1f, t1, c20 + c21));
    }
}

__global__ __launch_bounds__(NTHR, 4)
void potts_fused(const float* __restrict__ x, const float* __restrict__ y,
                 float* __restrict__ out) {
    __shared__ float s[5][SH][SW];   // 17280 B

    const int b   = blockIdx.z;
    const int tx0 = blockIdx.x * TW;
    const int ty0 = blockIdx.y * TH;
    const int tid = threadIdx.x;

    const float* xb = x + (size_t)b * 3 * PLANE;
    const float* yb = y + (size_t)b * 2 * PLANE;

    // Halo: rows ty0..ty0+11 (clamped at 255), cols tx0-4..tx0+67 (clamped).
    // Clamped garbage is only ever multiplied by a zero p/q-interior factor.
    for (int i = tid; i < 5 * SH * SW; i += NTHR) {
        int p  = i / (SH * SW);
        int r  = (i / SW) % SH;
        int c  = i % SW;
        int gy = min(ty0 + r, H - 1);
        int gx = min(max(tx0 - 4 + c, 0), W - 1);
        float v = (p < 3) ? xb[p * PLANE + gy * W + gx]
                          : yb[(p - 3) * PLANE + gy * W + gx];
        s[p][r][c] = v;
    }
    __syncthreads();

    const int lane = tid & 31;
    const int ly   = tid >> 5;          // warp = output row
    const int lx2  = lane * 2;
    const int gr   = ty0 + ly;
    const int gc0  = tx0 + lx2;

    // Interior tile: every p has pIn=1 AND every q=p+o (o in half-space) qIn=1.
    // p.r in [4,247], p.c in [8,247]  ->  bx in {1,2}, by in [1,30].
    const bool interior = (blockIdx.x == 1 || blockIdx.x == 2) &&
                          (blockIdx.y >= 1 && blockIdx.y <= 30);

    float acc = interior ? compute_pair<true >(s, ly, lx2, gr, gc0)
                         : compute_pair<false>(s, ly, lx2, gr, gc0);

    // Deterministic block reduction
    #pragma unroll
    for (int off = 16; off > 0; off >>= 1)
        acc += __shfl_down_sync(0xffffffffu, acc, off);

    __shared__ float wsum[NTHR / 32];
    if (lane == 0) wsum[ly] = acc;
    __syncthreads();

    __shared__ bool is_last;
    if (tid == 0) {
        float t = 0.0f;
        #pragma unroll
        for (int i = 0; i < NTHR / 32; i++) t += wsum[i];
        const int bid = blockIdx.x + GX * (blockIdx.y + GY * blockIdx.z);
        g_bsums[bid] = t;
        __threadfence();
        unsigned int old = atomicAdd(&g_count, 1u);
        is_last = (old == (unsigned)(NBLK - 1));
    }
    __syncthreads();

    if (is_last) {
        __threadfence();
        double dacc = 0.0;
        for (int i = tid; i < NBLK; i += NTHR) dacc += (double)g_bsums[i];
        #pragma unroll
        for (int off = 16; off > 0; off >>= 1)
            dacc += __shfl_down_sync(0xffffffffu, dacc, off);
        __shared__ double dsum[NTHR / 32];
        if (lane == 0) dsum[tid >> 5] = dacc;
        __syncthreads();
        if (tid == 0) {
            double t = 0.0;
            #pragma unroll
            for (int i = 0; i < NTHR / 32; i++) t += dsum[i];
            const double scale = 1.0 / ((double)B * 81.0 * (double)HO * (double)WO);
            out[0] = (float)(t * scale);
            g_count = 0;   // reset for next graph replay
        }
    }
}

extern "C" void kernel_launch(void* const* d_in, const int* in_sizes, int n_in,
                              void* d_out, int out_size) {
    const float* x = (const float*)d_in[0];   // [4,3,256,256]
    const float* y = (const float*)d_in[1];   // [4,2,256,256]
    float* out = (float*)d_out;

    // Bias the L1/shared split toward shared so >2 blocks can be resident.
    // Idempotent, not a stream op (safe under capture); errors ignored.
    cudaFuncSetAttribute(potts_fused,
                         cudaFuncAttributePreferredSharedMemoryCarveout,
                         cudaSharedmemCarveoutMaxShared);

    dim3 grid(GX, GY, B);
    potts_fused<<<grid, NTHR>>>(x, y, out);
}

// round 7
// speedup vs baseline: 1.0614x; 1.0614x over previous
#include <cuda_runtime.h>
#include <cuda_bf16.h>

// Problem constants
#define KSZ   9
#define PAD   4
#define H     256
#define W     256
#define HO    248
#define WO    248
#define B     4
#define PLANE (H * W)

// Tiling: block = 64x8 outputs over the FULL image; warp = one row, 2 cols/lane.
// Symmetric half-space formulation: offsets o = (0,1..4) and (1..4,-4..4) = 40 taps.
#define TW    64
#define TH    8
#define SW    72           // cols gc-4 .. gc+TW+3
#define SH    12           // rows r .. r+TH+3  (halo below only)
#define NTHR  256

#define GX    4
#define GY    32           // full 256 rows
#define NBLK  (GX * GY * B)   // 512

// -100 * log2(e) : exp(-color/0.01) = 2^(color * NC1)
#define NC1   (-144.26950408889634f)
// log2(e)/9      : dist = 2^(-d2_spatial * DC)
#define DC    (1.4426950408889634f / 9.0f)

typedef unsigned long long ull;

static __device__ float        g_bsums[NBLK];
static __device__ unsigned int g_count = 0;

__device__ __forceinline__ float ex2f(float v) {
    float r;
    asm("ex2.approx.f32 %0, %1;" : "=f"(r) : "f"(v));
    return r;
}
__device__ __forceinline__ ull pk(float lo, float hi) {
    ull r;
    asm("mov.b64 %0, {%1, %2};" : "=l"(r) : "f"(lo), "f"(hi));
    return r;
}
__device__ __forceinline__ void upk(ull v, float& lo, float& hi) {
    asm("mov.b64 {%0, %1}, %2;" : "=f"(lo), "=f"(hi) : "l"(v));
}
__device__ __forceinline__ ull f2add(ull a, ull b) {
    ull r;
    asm("add.rn.f32x2 %0, %1, %2;" : "=l"(r) : "l"(a), "l"(b));
    return r;
}
__device__ __forceinline__ ull f2mul(ull a, ull b) {
    ull r;
    asm("mul.rn.f32x2 %0, %1, %2;" : "=l"(r) : "l"(a), "l"(b));
    return r;
}
__device__ __forceinline__ ull f2fma(ull a, ull b, ull c) {
    ull r;
    asm("fma.rn.f32x2 %0, %1, %2, %3;" : "=l"(r) : "l"(a), "l"(b), "l"(c));
    return r;
}

// Per-thread compute over the 40 half-space offsets for a packed column pair.
// INTERIOR: every p in tile and every q=p+o are interior -> factor 2 folded out.
// Border:   total = pInF * (Sum w*m) + Sum w*m*qInF + pInF * 2*y0*y1(center).
template <bool INTERIOR>
__device__ __forceinline__ float compute_pair(
    float (&s)[5][SH][SW], int ly, int lx2, int gr, int gc0)
{
    const ull negc0 = pk(-s[0][ly][lx2 + 4], -s[0][ly][lx2 + 5]);
    const ull negc1 = pk(-s[1][ly][lx2 + 4], -s[1][ly][lx2 + 5]);
    const ull negc2 = pk(-s[2][ly][lx2 + 4], -s[2][ly][lx2 + 5]);
    const float y0c0 = s[3][ly][lx2 + 4], y0c1 = s[3][ly][lx2 + 5];
    const float y1c0 = s[4][ly][lx2 + 4], y1c1 = s[4][ly][lx2 + 5];
    const ull y0c_pk = pk(y0c0, y0c1);
    const ull y1c_pk = pk(y1c0, y1c1);

    ull accA = 0ull;   // Sum w * y1_q   (packed over col pair)
    ull accB = 0ull;   // Sum w * y0_q
    ull acc2 = 0ull;   // border only: Sum w * m * qInF

    #pragma unroll
    for (int di = 0; di < 5; di++) {
        const int sr = ly + di;
        float v0[10], v1[10], v2[10], q0[10], q1[10];
        const int m0 = (di == 0) ? 2 : 0;   // di==0 needs only cols +4..+9
        #pragma unroll
        for (int m = m0; m < 5; m++) {
            float2 t;
            t = *(const float2*)&s[0][sr][lx2 + 2*m]; v0[2*m] = t.x; v0[2*m+1] = t.y;
            t = *(const float2*)&s[1][sr][lx2 + 2*m]; v1[2*m] = t.x; v1[2*m+1] = t.y;
            t = *(const float2*)&s[2][sr][lx2 + 2*m]; v2[2*m] = t.x; v2[2*m+1] = t.y;
            t = *(const float2*)&s[3][sr][lx2 + 2*m]; q0[2*m] = t.x; q0[2*m+1] = t.y;
            t = *(const float2*)&s[4][sr][lx2 + 2*m]; q1[2*m] = t.x; q1[2*m+1] = t.y;
        }
        bool rqOK = true;
        if (!INTERIOR) {
            const int rq = gr + di;
            rqOK = (rq >= 4) && (rq <= 251);
        }
        const int djs = (di == 0) ? 1 : -4;
        #pragma unroll
        for (int dj = djs; dj <= 4; dj++) {
            const int j = dj + 4;
            ull n0 = pk(v0[j], v0[j + 1]);
            ull n1 = pk(v1[j], v1[j + 1]);
            ull n2 = pk(v2[j], v2[j + 1]);
            ull d0 = f2add(n0, negc0);
            ull d1 = f2add(n1, negc1);
            ull d2 = f2add(n2, negc2);
            ull c  = f2mul(d0, d0);
            c = f2fma(d1, d1, c);
            c = f2fma(d2, d2, c);
            float clo, chi;
            upk(c, clo, chi);
            const float c0k = -(float)(di * di + dj * dj) * DC;
            ull w = pk(ex2f(fmaf(clo, NC1, c0k)), ex2f(fmaf(chi, NC1, c0k)));
            ull ny0 = pk(q0[j], q0[j + 1]);
            ull ny1 = pk(q1[j], q1[j + 1]);
            accA = f2fma(w, ny1, accA);
            accB = f2fma(w, ny0, accB);
            if (!INTERIOR) {
                ull m2 = f2fma(y1c_pk, ny0, f2mul(y0c_pk, ny1));
                float qf0 = (rqOK && (unsigned)(gc0 + dj - 4) <= 247u) ? 1.0f : 0.0f;
                float qf1 = (rqOK && (unsigned)(gc0 + 1 + dj - 4) <= 247u) ? 1.0f : 0.0f;
                acc2 = f2fma(w, f2mul(m2, pk(qf0, qf1)), acc2);
            }
        }
    }

    float a0, a1, b0, b1;
    upk(accA, a0, a1);
    upk(accB, b0, b1);
    const float tc0 = y0c0 * y1c0;   // center (o=0): contributes [p in I]*2*y0*y1
    const float tc1 = y0c1 * y1c1;

    if (INTERIOR) {
        // all p,q interior -> factor 2 on every pair incl. center
        return 2.0f * (fmaf(y0c0, a0, fmaf(y1c0, b0, tc0)) +
                       fmaf(y0c1, a1, fmaf(y1c1, b1, tc1)));
    } else {
        const bool rOK = (unsigned)(gr - 4) <= 247u;
        const float p0f = (rOK && (unsigned)(gc0 - 4) <= 247u) ? 1.0f : 0.0f;
        const float p1f = (rOK && (unsigned)(gc0 - 3) <= 247u) ? 1.0f : 0.0f;
        float c20, c21;
        upk(acc2, c20, c21);
        const float t0 = fmaf(y0c0, a0, fmaf(y1c0, b0, 2.0f * tc0));
        const float t1 = fmaf(y0c1, a1, fmaf(y1c1, b1, 2.0f * tc1));
        return fmaf(p0f, t0, fmaf(p1f, t1, c20 + c21));
    }
}

// 2 blocks/SM: register budget ~128 -> no spills in the border path.
__global__ __launch_bounds__(NTHR, 2)
void potts_fused(const float* __restrict__ x, const float* __restrict__ y,
                 float* __restrict__ out) {
    __shared__ float s[5][SH][SW];   // 17280 B

    const int b   = blockIdx.z;
    const int tx0 = blockIdx.x * TW;
    const int ty0 = blockIdx.y * TH;
    const int tid = threadIdx.x;

    const float* xb = x + (size_t)b * 3 * PLANE;
    const float* yb = y + (size_t)b * 2 * PLANE;

    // Halo: rows ty0..ty0+11 (clamped at 255), cols tx0-4..tx0+67 (clamped).
    // Clamped garbage is only ever multiplied by a zero p/q-interior factor.
    for (int i = tid; i < 5 * SH * SW; i += NTHR) {
        int p  = i / (SH * SW);
        int r  = (i / SW) % SH;
        int c  = i % SW;
        int gy = min(ty0 + r, H - 1);
        int gx = min(max(tx0 - 4 + c, 0), W - 1);
        float v = (p < 3) ? xb[p * PLANE + gy * W + gx]
                          : yb[(p - 3) * PLANE + gy * W + gx];
        s[p][r][c] = v;
    }
    __syncthreads();

    const int lane = tid & 31;
    const int ly   = tid >> 5;          // warp = output row
    const int lx2  = lane * 2;
    const int gr   = ty0 + ly;
    const int gc0  = tx0 + lx2;

    // Interior tile: every p has pIn=1 AND every q=p+o (o in half-space) qIn=1.
    // p.r in [4,247], p.c in [8,247]  ->  bx in {1,2}, by in [1,30].
    const bool interior = (blockIdx.x == 1 || blockIdx.x == 2) &&
                          (blockIdx.y >= 1 && blockIdx.y <= 30);

    float acc = interior ? compute_pair<true >(s, ly, lx2, gr, gc0)
                         : compute_pair<false>(s, ly, lx2, gr, gc0);

    // Deterministic block reduction
    #pragma unroll
    for (int off = 16; off > 0; off >>= 1)
        acc += __shfl_down_sync(0xffffffffu, acc, off);

    __shared__ float wsum[NTHR / 32];
    if (lane == 0) wsum[ly] = acc;
    __syncthreads();

    __shared__ bool is_last;
    if (tid == 0) {
        float t = 0.0f;
        #pragma unroll
        for (int i = 0; i < NTHR / 32; i++) t += wsum[i];
        const int bid = blockIdx.x + GX * (blockIdx.y + GY * blockIdx.z);
        g_bsums[bid] = t;
        __threadfence();
        unsigned int old = atomicAdd(&g_count, 1u);
        is_last = (old == (unsigned)(NBLK - 1));
    }
    __syncthreads();

    if (is_last) {
        __threadfence();
        double dacc = 0.0;
        for (int i = tid; i < NBLK; i += NTHR) dacc += (double)g_bsums[i];
        #pragma unroll
        for (int off = 16; off > 0; off >>= 1)
            dacc += __shfl_down_sync(0xffffffffu, dacc, off);
        __shared__ double dsum[NTHR / 32];
        if (lane == 0) dsum[tid >> 5] = dacc;
        __syncthreads();
        if (tid == 0) {
            double t = 0.0;
            #pragma unroll
            for (int i = 0; i < NTHR / 32; i++) t += dsum[i];
            const double scale = 1.0 / ((double)B * 81.0 * (double)HO * (double)WO);
            out[0] = (float)(t * scale);
            g_count = 0;   // reset for next graph replay
        }
    }
}

extern "C" void kernel_launch(void* const* d_in, const int* in_sizes, int n_in,
                              void* d_out, int out_size) {
    const float* x = (const float*)d_in[0];   // [4,3,256,256]
    const float* y = (const float*)d_in[1];   // [4,2,256,256]
    float* out = (float*)d_out;

    dim3 grid(GX, GY, B);
    potts_fused<<<grid, NTHR>>>(x, y, out);
}